// round 9
// baseline (speedup 1.0000x reference)
#include <cuda_runtime.h>
#include <cstdint>

// MeanAggregator: out[b, :] = mean_{s<S} features[neigh_idx[b,s], :]
// B=50000, S=10, N=1e6, D=128 (fp32).
//
// Persistent-block variant: grid = 148 SMs * 8 blocks, each warp strides over
// output rows. Eliminates the partial final wave (6250 blocks / 1184 resident
// = 5.28 waves previously) and lets the compiler overlap next-row index loads
// with current-row arithmetic, densifying the LSU request stream.
//
// Per row: one warp, each lane owns one float4 column (32*16B = 512B = one
// full feature row per LDG wave, fully coalesced). Indices preloaded as
// uint32 BYTE offsets (idx*512 < 2^32).
//
// L2 policy: streaming (evict-first) for write-once output and read-once
// indices, protecting the reusable feature lines.
//
// Index dtype (int32 vs int64) detected inline once per warp: odd 32-bit
// words of the first 4 elements are all zero iff little-endian int64 with
// values < 2^31 (false-positive P ~ 1e-24 for random int32 in [0,1e6)).

#define AGG_B 50000
#define AGG_S 10
#define AGG_D 128
#define AGG_VEC (AGG_D / 4)   // 32 float4 per row == one per lane

#define AGG_SMS 148
#define AGG_BLOCKS_PER_SM 8
#define AGG_GRID (AGG_SMS * AGG_BLOCKS_PER_SM)   // 1184 persistent blocks

__global__ __launch_bounds__(256, AGG_BLOCKS_PER_SM) void mean_agg_kernel(
    const unsigned* __restrict__ idx_raw,     // [B,S] int32 OR int64 words
    const char* __restrict__ features,        // [N, 512B rows]
    float4* __restrict__ out)                 // [B, 32] as float4
{
    const int gtid    = blockIdx.x * blockDim.x + threadIdx.x;
    const int warp    = gtid >> 5;                       // global warp id
    const int lane    = gtid & 31;                       // float4 column
    const int n_warps = (AGG_GRID * 256) >> 5;           // 9472

    // Inline dtype detection, once per warp (one broadcast sector)
    const unsigned w1 = __ldg(idx_raw + 1);
    const unsigned w3 = __ldg(idx_raw + 3);
    const unsigned w5 = __ldg(idx_raw + 5);
    const unsigned w7 = __ldg(idx_raw + 7);
    const bool is64 = ((w1 | w3 | w5 | w7) == 0u);

    const char* fb = features + lane * 16;   // hoisted lane offset

    for (int row = warp; row < AGG_B; row += n_warps) {
        // Preload all S indices as byte offsets (broadcast streaming loads)
        unsigned off[AGG_S];
        if (is64) {
            const unsigned* nb = idx_raw + (size_t)row * AGG_S * 2;
#pragma unroll
            for (int s = 0; s < AGG_S; s++)
                off[s] = __ldcs(nb + 2 * s) << 9;        // idx * 512
        } else {
            const unsigned* nb = idx_raw + row * AGG_S;
#pragma unroll
            for (int s = 0; s < AGG_S; s++)
                off[s] = __ldcs(nb + s) << 9;            // idx * 512
        }

        float4 acc = make_float4(0.f, 0.f, 0.f, 0.f);
#pragma unroll
        for (int s = 0; s < AGG_S; s++) {
            float4 v = __ldg((const float4*)(fb + off[s]));
            acc.x += v.x; acc.y += v.y; acc.z += v.z; acc.w += v.w;
        }

        const float inv = 1.0f / (float)AGG_S;
        acc.x *= inv; acc.y *= inv; acc.z *= inv; acc.w *= inv;

        // Streaming store: write-once output must not evict feature lines
        __stcs(&out[row * AGG_VEC + lane], acc);
    }
}

extern "C" void kernel_launch(void* const* d_in, const int* in_sizes, int n_in,
                              void* d_out, int out_size)
{
    const unsigned* neigh_idx = (const unsigned*)d_in[0];  // [B,S] i32/i64
    const char*     features  = (const char*)d_in[1];      // fp32 [N, D]
    float4*         out       = (float4*)d_out;            // fp32 [B, D]

    mean_agg_kernel<<<AGG_GRID, 256>>>(neigh_idx, features, out);
}

// round 10
// speedup vs baseline: 1.0007x; 1.0007x over previous
#include <cuda_runtime.h>
#include <cstdint>

// MeanAggregator: out[b, :] = mean_{s<S} features[neigh_idx[b,s], :]
// B=50000, S=10, N=1e6, D=128 (fp32).
//
// One-shot warps (persistent-loop variant regressed: loop-carried off[]/acc
// dependencies expose idx-load latency per row; block retirement overlaps
// naturally). TWO rows per warp (row, row+B/2): 20 independent LDG.128 in
// flight per warp to push DRAM busy% higher, half the broadcast idx stalls,
// half the blocks (shorter tail).
//
// Each lane owns one float4 column: 32*16B = 512B = one full feature row per
// LDG wave, fully coalesced. Indices preloaded as uint32 BYTE offsets
// (idx*512 < 2^32).
//
// L2 policy: streaming (evict-first) for write-once output and read-once
// indices, protecting reusable feature lines.
//
// Index dtype (int32 vs int64) detected inline: odd 32-bit words of the first
// 4 elements all zero iff little-endian int64 with values < 2^31.

#define AGG_B 50000
#define AGG_H (AGG_B / 2)     // 25000 warps, 2 rows each
#define AGG_S 10
#define AGG_D 128
#define AGG_VEC (AGG_D / 4)   // 32 float4 per row == one per lane

__global__ __launch_bounds__(256, 6) void mean_agg_kernel(
    const unsigned* __restrict__ idx_raw,     // [B,S] int32 OR int64 words
    const char* __restrict__ features,        // [N, 512B rows]
    float4* __restrict__ out)                 // [B, 32] as float4
{
    const int gtid = blockIdx.x * blockDim.x + threadIdx.x;
    const int warp = gtid >> 5;
    const int lane = gtid & 31;
    if (warp >= AGG_H) return;

    const int rowA = warp;
    const int rowB = warp + AGG_H;

    // Inline dtype detection (one broadcast sector, L1-resident after warp 0)
    const unsigned w1 = __ldg(idx_raw + 1);
    const unsigned w3 = __ldg(idx_raw + 3);
    const unsigned w5 = __ldg(idx_raw + 5);
    const unsigned w7 = __ldg(idx_raw + 7);
    const bool is64 = ((w1 | w3 | w5 | w7) == 0u);

    // Preload all 2*S indices as byte offsets (broadcast streaming loads)
    unsigned offA[AGG_S], offB[AGG_S];
    if (is64) {
        const unsigned* na = idx_raw + (size_t)rowA * AGG_S * 2;
        const unsigned* nb = idx_raw + (size_t)rowB * AGG_S * 2;
#pragma unroll
        for (int s = 0; s < AGG_S; s++) {
            offA[s] = __ldcs(na + 2 * s) << 9;           // idx * 512
            offB[s] = __ldcs(nb + 2 * s) << 9;
        }
    } else {
        const unsigned* na = idx_raw + rowA * AGG_S;
        const unsigned* nb = idx_raw + rowB * AGG_S;
#pragma unroll
        for (int s = 0; s < AGG_S; s++) {
            offA[s] = __ldcs(na + s) << 9;               // idx * 512
            offB[s] = __ldcs(nb + s) << 9;
        }
    }

    const char* fb = features + lane * 16;   // hoisted lane offset

    float4 accA = make_float4(0.f, 0.f, 0.f, 0.f);
    float4 accB = make_float4(0.f, 0.f, 0.f, 0.f);
#pragma unroll
    for (int s = 0; s < AGG_S; s++) {
        float4 vA = __ldg((const float4*)(fb + offA[s]));
        float4 vB = __ldg((const float4*)(fb + offB[s]));
        accA.x += vA.x; accA.y += vA.y; accA.z += vA.z; accA.w += vA.w;
        accB.x += vB.x; accB.y += vB.y; accB.z += vB.z; accB.w += vB.w;
    }

    const float inv = 1.0f / (float)AGG_S;
    accA.x *= inv; accA.y *= inv; accA.z *= inv; accA.w *= inv;
    accB.x *= inv; accB.y *= inv; accB.z *= inv; accB.w *= inv;

    // Streaming stores: write-once output must not evict feature lines
    __stcs(&out[rowA * AGG_VEC + lane], accA);
    __stcs(&out[rowB * AGG_VEC + lane], accB);
}

extern "C" void kernel_launch(void* const* d_in, const int* in_sizes, int n_in,
                              void* d_out, int out_size)
{
    const unsigned* neigh_idx = (const unsigned*)d_in[0];  // [B,S] i32/i64
    const char*     features  = (const char*)d_in[1];      // fp32 [N, D]
    float4*         out       = (float4*)d_out;            // fp32 [B, D]

    const int threads = 256;                       // 8 warps / block
    const int total_threads = AGG_H * 32;          // one warp per 2 rows
    const int blocks = (total_threads + threads - 1) / threads;   // 3125
    mean_agg_kernel<<<blocks, threads>>>(neigh_idx, features, out);
}

// round 11
// speedup vs baseline: 1.0502x; 1.0494x over previous
#include <cuda_runtime.h>
#include <cstdint>

// MeanAggregator: out[b, :] = mean_{s<S} features[neigh_idx[b,s], :]
// B=50000, S=10, N=1e6, D=128 (fp32).
//
// Structure locked in by R7/R9/R10 A-Bs: ONE row per warp, one-shot blocks
// (32 regs -> 87% occupancy; both persistent loops and 2-rows/warp regressed
// by costing occupancy or serializing on index loads).
//
// This round: indices fetched with ONE lane-parallel coalesced LDG (lanes
// 0..9 for int32, 0..19 for int64 words) + SHFL.IDX distribution, instead of
// 10 broadcast loads -> first gather issues one load-latency sooner, 10x
// fewer idx LSU ops. 128-thread blocks (16/SM) for finer retirement/tail.
//
// Each lane owns one float4 column: 32*16B = 512B = one full feature row per
// LDG wave, fully coalesced. Offsets are uint32 BYTE offsets (idx*512 < 2^32).
// Streaming policy (__ldcs/__stcs) for read-once indices / write-once output.
//
// Index dtype (int32 vs int64) detected inline: odd 32-bit words of the first
// 4 elements all zero iff little-endian int64 with values < 2^31.

#define AGG_B 50000
#define AGG_S 10
#define AGG_D 128
#define AGG_VEC (AGG_D / 4)   // 32 float4 per row == one per lane

__global__ __launch_bounds__(128, 16) void mean_agg_kernel(
    const unsigned* __restrict__ idx_raw,     // [B,S] int32 OR int64 words
    const char* __restrict__ features,        // [N, 512B rows]
    float4* __restrict__ out)                 // [B, 32] as float4
{
    const int gtid = blockIdx.x * blockDim.x + threadIdx.x;
    const int row  = gtid >> 5;          // warp id == output row
    const int lane = gtid & 31;          // lane == float4 column
    if (row >= AGG_B) return;

    // Inline dtype detection (one broadcast sector, L1-resident after warp 0)
    const unsigned w1 = __ldg(idx_raw + 1);
    const unsigned w3 = __ldg(idx_raw + 3);
    const unsigned w5 = __ldg(idx_raw + 5);
    const unsigned w7 = __ldg(idx_raw + 7);
    const bool is64 = ((w1 | w3 | w5 | w7) == 0u);

    // ONE lane-parallel coalesced index load, then shuffle-distribute.
    unsigned myw = 0;
    if (is64) {
        if (lane < 2 * AGG_S)
            myw = __ldcs(idx_raw + (size_t)row * (2 * AGG_S) + lane);
    } else {
        if (lane < AGG_S)
            myw = __ldcs(idx_raw + row * AGG_S + lane);
    }
    const int stride = is64 ? 2 : 1;     // word position of element s

    unsigned off[AGG_S];
#pragma unroll
    for (int s = 0; s < AGG_S; s++)
        off[s] = __shfl_sync(0xffffffffu, myw, s * stride) << 9;  // idx*512

    const char* fb = features + lane * 16;   // hoisted lane offset

    float4 acc = make_float4(0.f, 0.f, 0.f, 0.f);
#pragma unroll
    for (int s = 0; s < AGG_S; s++) {
        float4 v = __ldg((const float4*)(fb + off[s]));
        acc.x += v.x; acc.y += v.y; acc.z += v.z; acc.w += v.w;
    }

    const float inv = 1.0f / (float)AGG_S;
    acc.x *= inv; acc.y *= inv; acc.z *= inv; acc.w *= inv;

    // Streaming store: write-once output must not evict feature lines
    __stcs(&out[row * AGG_VEC + lane], acc);
}

extern "C" void kernel_launch(void* const* d_in, const int* in_sizes, int n_in,
                              void* d_out, int out_size)
{
    const unsigned* neigh_idx = (const unsigned*)d_in[0];  // [B,S] i32/i64
    const char*     features  = (const char*)d_in[1];      // fp32 [N, D]
    float4*         out       = (float4*)d_out;            // fp32 [B, D]

    const int threads = 128;                       // 4 warps / block
    const int total_threads = AGG_B * 32;          // one warp per row
    const int blocks = (total_threads + threads - 1) / threads;   // 12500
    mean_agg_kernel<<<blocks, threads>>>(neigh_idx, features, out);
}